// round 15
// baseline (speedup 1.0000x reference)
#include <cuda_runtime.h>
#include <cuda_fp16.h>
#include <cstdint>
#include <cstddef>

// ---------------------------------------------------------------------------
// Problem constants
// ---------------------------------------------------------------------------
#define NN   100000
#define NE   100000
#define DIM  768
#define DIM2 1536
#define NT   5
#define LN_EPS 1e-5f

// fp16 GEMM: CTA 128x256, 8 warps 2x4, warp tile 64x64, BK=64 halves,
// 4 stages x 48KB (193KB smem, 1 CTA/SM), XOR-swizzled 16B chunks,
// 1 barrier/slice, prefetch depth 3.
#define BM 128
#define BN 256
#define BK 64                   // halves per stage (128 B per row)
#define THREADS 256
#define ROWU 32                 // unsigned per smem row (128 B)
#define A_STG_BYTES (BM * 128)  // 16384
#define B_STG_BYTES (BN * 128)  // 32768
#define STG_BYTES   (A_STG_BYTES + B_STG_BYTES)  // 49152
#define NSTG 4
#define SM_IDX   0
#define SM_TILES 1024
#define SMEM_SZ  (SM_TILES + NSTG * STG_BYTES)   // 197632

// ---------------------------------------------------------------------------
// Device scratch (uint4 arrays for 16B alignment; viewed as __half).
// fp16 data K-PERMUTED within each 32-half group:
//   phys(l) = 8*((l>>1)&3) + 2*((l>>3)&3) + (l&1)
// ---------------------------------------------------------------------------
__device__ uint4 g_agg_v [(size_t)NN * DIM / 8];
__device__ uint4 g_xtf_v [(size_t)NN * DIM / 8];
__device__ uint4 g_wmtf_v[(size_t)NT * DIM * DIM / 8];
__device__ uint4 g_wutf_v[(size_t)DIM * DIM2 / 8];
__device__ int   g_bucket[NT][NE];
__device__ int   g_count[NT];

// ---------------------------------------------------------------------------
// Helpers
// ---------------------------------------------------------------------------
__device__ __forceinline__ uint32_t smem_u32(const void* p) {
    uint32_t a;
    asm("{ .reg .u64 t; cvta.to.shared.u64 t, %1; cvt.u32.u64 %0, t; }"
        : "=r"(a) : "l"(p));
    return a;
}

__device__ __forceinline__ void cpa16(uint32_t s, const void* g) {
    asm volatile("cp.async.cg.shared.global [%0], [%1], 16;"
                 :: "r"(s), "l"(g) : "memory");
}
__device__ __forceinline__ void cpa_commit() {
    asm volatile("cp.async.commit_group;" ::: "memory");
}
__device__ __forceinline__ void cpa_wait2() {
    asm volatile("cp.async.wait_group 2;" ::: "memory");
}

__device__ __forceinline__ void mma16(float& c0, float& c1, float& c2, float& c3,
                                      unsigned a0, unsigned a1, unsigned a2, unsigned a3,
                                      unsigned b0, unsigned b1) {
    asm volatile(
        "mma.sync.aligned.m16n8k16.row.col.f32.f16.f16.f32 "
        "{%0,%1,%2,%3}, {%4,%5,%6,%7}, {%8,%9}, {%0,%1,%2,%3};\n"
        : "+f"(c0), "+f"(c1), "+f"(c2), "+f"(c3)
        : "r"(a0), "r"(a1), "r"(a2), "r"(a3), "r"(b0), "r"(b1));
}

// one BK=64 slice on a 64x64 warp tile: 2 kp-groups x 2 k16-steps each.
__device__ __forceinline__ void compute_stage(const unsigned* __restrict__ As,
                                              const unsigned* __restrict__ Bs,
                                              float c[4][8][4],
                                              int wm, int wn, int g, int tg) {
    int xorv = (g & 1) << 2;
#pragma unroll
    for (int kp = 0; kp < 2; ++kp) {
        int cu = ((4 * kp + tg) ^ xorv) * 4;   // unsigned offset within row
        uint4 a[4][2], b[8];
#pragma unroll
        for (int im = 0; im < 4; ++im) {
            int mb = wm * 64 + im * 16;
            a[im][0] = *reinterpret_cast<const uint4*>(&As[(mb + g) * ROWU + cu]);
            a[im][1] = *reinterpret_cast<const uint4*>(&As[(mb + g + 8) * ROWU + cu]);
        }
#pragma unroll
        for (int in_ = 0; in_ < 8; ++in_) {
            int nb = wn * 64 + in_ * 8 + g;
            b[in_] = *reinterpret_cast<const uint4*>(&Bs[nb * ROWU + cu]);
        }
#pragma unroll
        for (int im = 0; im < 4; ++im)
#pragma unroll
            for (int in_ = 0; in_ < 8; ++in_) {
                mma16(c[im][in_][0], c[im][in_][1], c[im][in_][2], c[im][in_][3],
                      a[im][0].x, a[im][1].x, a[im][0].y, a[im][1].y,
                      b[in_].x, b[in_].y);
                mma16(c[im][in_][0], c[im][in_][1], c[im][in_][2], c[im][in_][3],
                      a[im][0].z, a[im][1].z, a[im][0].w, a[im][1].w,
                      b[in_].z, b[in_].w);
            }
    }
}

// ---------------------------------------------------------------------------
// K0 / K1: init + bucket
// ---------------------------------------------------------------------------
__global__ void k_init() {
    size_t idx = (size_t)blockIdx.x * blockDim.x + threadIdx.x;
    if (idx < NT) g_count[idx] = 0;
    size_t n = (size_t)NN * DIM / 8;
    size_t stride = (size_t)gridDim.x * blockDim.x;
    uint4 z = make_uint4(0, 0, 0, 0);
    for (size_t i = idx; i < n; i += stride) g_agg_v[i] = z;
}

__global__ void k_bucket(const int* __restrict__ etype) {
    int e = blockIdx.x * blockDim.x + threadIdx.x;
    if (e < NE) {
        int t = etype[e];
        int pos = atomicAdd(&g_count[t], 1);
        g_bucket[t][pos] = e;
    }
}

// f32 -> fp16(rn) + K-permute one 32-float group
__device__ __forceinline__ void cvtph_group(const float* src, __half* dst, size_t i) {
    const float4* s = reinterpret_cast<const float4*>(src) + i * 8;
    float in[32];
#pragma unroll
    for (int j = 0; j < 8; ++j) {
        float4 v = s[j];
        in[j * 4] = v.x; in[j * 4 + 1] = v.y; in[j * 4 + 2] = v.z; in[j * 4 + 3] = v.w;
    }
    __half2 out[16];
#pragma unroll
    for (int ph = 0; ph < 16; ++ph) {
        int p = ph * 2;                               // even phys index
        int l = ((p >> 3) << 1) + (((p >> 1) & 3) << 3);  // logical index
        out[ph] = __floats2half2_rn(in[l], in[l + 1]);
    }
    uint4* d = reinterpret_cast<uint4*>(dst + i * 32);
    const uint4* o = reinterpret_cast<const uint4*>(out);
    d[0] = o[0]; d[1] = o[1]; d[2] = o[2]; d[3] = o[3];
}

__global__ void k_cvtp3(const float* s0, __half* d0, size_t n0,
                        const float* s1, __half* d1, size_t n1,
                        const float* s2, __half* d2, size_t n2) {
    size_t idx = (size_t)blockIdx.x * blockDim.x + threadIdx.x;
    size_t stride = (size_t)gridDim.x * blockDim.x;
    size_t total = n0 + n1 + n2;
    for (size_t i = idx; i < total; i += stride) {
        if (i < n0) cvtph_group(s0, d0, i);
        else if (i < n0 + n1) cvtph_group(s1, d1, i - n0);
        else cvtph_group(s2, d2, i - n0 - n1);
    }
}

// ---------------------------------------------------------------------------
// K2: per-type gather-GEMM (fp16); epilogue rounds to fp16 and half2-atomic
//     scatter-adds into PERMUTED g_agg. grid (3, 782, 5), 256 thr, 1 CTA/SM
// ---------------------------------------------------------------------------
__global__ __launch_bounds__(THREADS, 1) void k_msg(const float* __restrict__ bm,
                                                    const int*   __restrict__ eidx) {
    int t = blockIdx.z;
    int cnt = g_count[t];
    int m0 = blockIdx.y * BM;
    if (m0 >= cnt) return;
    int n0 = blockIdx.x * BN;

    extern __shared__ char smem[];
    uint32_t sb = smem_u32(smem);
    int* s_src = (int*)(smem + SM_IDX);
    int* s_tgt = (int*)(smem + SM_IDX + 512);

    int tid = threadIdx.x, lane = tid & 31, w = tid >> 5;
    int wm = w >> 2, wn = w & 3;
    int g = lane >> 2, tg = lane & 3;

    if (tid < BM) {
        int slot = m0 + tid;
        if (slot < cnt) {
            int e = g_bucket[t][slot];
            s_src[tid] = eidx[e];
            s_tgt[tid] = eidx[NE + e];
        } else {
            s_src[tid] = 0;
            s_tgt[tid] = -1;
        }
    }
    __syncthreads();

    const __half* Xh = (const __half*)g_xtf_v;
    const __half* Wt = (const __half*)g_wmtf_v + (size_t)t * DIM * DIM;

    // fill: A 128x8=1024 chunks (p<4), B 256x8=2048 chunks (p<8); 256 threads
    auto fill = [&](int stg, int kk) {
        uint32_t ab = sb + SM_TILES + stg * STG_BYTES;
        uint32_t bbs = ab + A_STG_BYTES;
#pragma unroll
        for (int p = 0; p < 4; ++p) {
            int f = p * THREADS + tid;
            int row = f >> 3, q = f & 7;
            int qs = q ^ ((row & 1) << 2);
            cpa16(ab + row * 128 + qs * 16,
                  Xh + (size_t)s_src[row] * DIM + kk + q * 8);
        }
#pragma unroll
        for (int p = 0; p < 8; ++p) {
            int f = p * THREADS + tid;
            int row = f >> 3, q = f & 7;
            int qs = q ^ ((row & 1) << 2);
            cpa16(bbs + row * 128 + qs * 16,
                  Wt + (size_t)(n0 + row) * DIM + kk + q * 8);
        }
    };

    float c[4][8][4];
#pragma unroll
    for (int i = 0; i < 4; i++)
#pragma unroll
        for (int j = 0; j < 8; j++)
#pragma unroll
            for (int r = 0; r < 4; r++) c[i][j][r] = 0.f;

    const int KT = DIM / BK;   // 12
    fill(0, 0);      cpa_commit();
    fill(1, BK);     cpa_commit();
    fill(2, 2 * BK); cpa_commit();

    for (int kt = 0; kt < KT; ++kt) {
        cpa_wait2();           // groups <= kt complete (3 committed ahead)
        __syncthreads();       // stage kt%4 ready for all; kt-1 reads done
        const unsigned* As = (const unsigned*)(smem + SM_TILES + (kt % NSTG) * STG_BYTES);
        const unsigned* Bs = As + BM * ROWU;
        compute_stage(As, Bs, c, wm, wn, g, tg);
        if (kt + 3 < KT) fill((kt + 3) % NSTG, (kt + 3) * BK);
        cpa_commit();          // unconditional: exact group accounting
    }

    // epilogue: + bias, fp16-round, half2 atomic into PERMUTED g_agg.
    __half* aggh = (__half*)g_agg_v;
#pragma unroll
    for (int im = 0; im < 4; ++im) {
#pragma unroll
        for (int r2 = 0; r2 < 2; ++r2) {
            int rloc = wm * 64 + im * 16 + g + r2 * 8;
            int tgt = s_tgt[rloc];
            if (tgt < 0) continue;
            __half* dst = aggh + (size_t)tgt * DIM;
#pragma unroll
            for (int in_ = 0; in_ < 8; ++in_) {
                int col = n0 + wn * 64 + in_ * 8 + tg * 2;
                int base = col & ~31;
                int l32 = col & 31;
                int p = (((l32 >> 1) & 3) << 3) + (((l32 >> 3) & 3) << 1);
                float v0 = c[im][in_][r2 * 2 + 0] + bm[t * DIM + col];
                float v1 = c[im][in_][r2 * 2 + 1] + bm[t * DIM + col + 1];
                atomicAdd(reinterpret_cast<__half2*>(dst + base + p),
                          __floats2half2_rn(v0, v1));
            }
        }
    }
}

// ---------------------------------------------------------------------------
// K3: update GEMM (fp16)  out = relu([X | agg] @ W_upd^T + b_upd)
//     grid (3, 782), 256 threads, 1 CTA/SM
// ---------------------------------------------------------------------------
__global__ __launch_bounds__(THREADS, 1) void k_upd(const float* __restrict__ bu,
                                                    float* __restrict__ out) {
    int m0 = blockIdx.y * BM;
    int n0 = blockIdx.x * BN;

    extern __shared__ char smem[];
    uint32_t sb = smem_u32(smem);

    int tid = threadIdx.x, lane = tid & 31, w = tid >> 5;
    int wm = w >> 2, wn = w & 3;
    int g = lane >> 2, tg = lane & 3;

    const __half* Xh = (const __half*)g_xtf_v;
    const __half* Ah = (const __half*)g_agg_v;
    const __half* Wu = (const __half*)g_wutf_v;

    auto fill = [&](int stg, int kk) {
        uint32_t ab = sb + SM_TILES + stg * STG_BYTES;
        uint32_t bbs = ab + A_STG_BYTES;
        const __half* abase = (kk < DIM) ? Xh + kk : Ah + (kk - DIM);
#pragma unroll
        for (int p = 0; p < 4; ++p) {
            int f = p * THREADS + tid;
            int row = f >> 3, q = f & 7;
            int qs = q ^ ((row & 1) << 2);
            int node = m0 + row; if (node >= NN) node = NN - 1;
            cpa16(ab + row * 128 + qs * 16, abase + (size_t)node * DIM + q * 8);
        }
#pragma unroll
        for (int p = 0; p < 8; ++p) {
            int f = p * THREADS + tid;
            int row = f >> 3, q = f & 7;
            int qs = q ^ ((row & 1) << 2);
            cpa16(bbs + row * 128 + qs * 16,
                  Wu + (size_t)(n0 + row) * DIM2 + kk + q * 8);
        }
    };

    float c[4][8][4];
#pragma unroll
    for (int i = 0; i < 4; i++)
#pragma unroll
        for (int j = 0; j < 8; j++)
#pragma unroll
            for (int r = 0; r < 4; r++) c[i][j][r] = 0.f;

    const int KT = DIM2 / BK;  // 24
    fill(0, 0);      cpa_commit();
    fill(1, BK);     cpa_commit();
    fill(2, 2 * BK); cpa_commit();

    for (int kt = 0; kt < KT; ++kt) {
        cpa_wait2();
        __syncthreads();
        const unsigned* As = (const unsigned*)(smem + SM_TILES + (kt % NSTG) * STG_BYTES);
        const unsigned* Bs = As + BM * ROWU;
        compute_stage(As, Bs, c, wm, wn, g, tg);
        if (kt + 3 < KT) fill((kt + 3) % NSTG, (kt + 3) * BK);
        cpa_commit();
    }

    // epilogue: bias + relu, float2 stores
#pragma unroll
    for (int im = 0; im < 4; ++im) {
#pragma unroll
        for (int r2 = 0; r2 < 2; ++r2) {
            int rloc = wm * 64 + im * 16 + g + r2 * 8;
            int node = m0 + rloc;
            if (node >= NN) continue;
#pragma unroll
            for (int in_ = 0; in_ < 8; ++in_) {
                int col = n0 + wn * 64 + in_ * 8 + tg * 2;
                float2 o;
                o.x = fmaxf(c[im][in_][r2 * 2 + 0] + bu[col],     0.f);
                o.y = fmaxf(c[im][in_][r2 * 2 + 1] + bu[col + 1], 0.f);
                *reinterpret_cast<float2*>(out + (size_t)node * DIM + col) = o;
            }
        }
    }
}

// ---------------------------------------------------------------------------
// K4: out = LayerNorm(X + out)   (full-precision X residual)
// ---------------------------------------------------------------------------
__global__ __launch_bounds__(256) void k_ln(float* __restrict__ out,
                                            const float* __restrict__ X,
                                            const float* __restrict__ gamma,
                                            const float* __restrict__ beta) {
    __shared__ float red[34];
    int n = blockIdx.x;
    float* row = out + (size_t)n * DIM;
    const float* xr = X + (size_t)n * DIM;
    int tid = threadIdx.x;

    float v0 = row[tid]       + xr[tid];
    float v1 = row[tid + 256] + xr[tid + 256];
    float v2 = row[tid + 512] + xr[tid + 512];
    float s = v0 + v1 + v2;
    float s2 = v0 * v0 + v1 * v1 + v2 * v2;
#pragma unroll
    for (int o = 16; o > 0; o >>= 1) {
        s  += __shfl_xor_sync(0xffffffffu, s, o);
        s2 += __shfl_xor_sync(0xffffffffu, s2, o);
    }
    int w = tid >> 5, l = tid & 31;
    if (l == 0) { red[w] = s; red[8 + w] = s2; }
    __syncthreads();
    if (w == 0) {
        float a = (l < 8) ? red[l] : 0.f;
        float b = (l < 8) ? red[8 + l] : 0.f;
#pragma unroll
        for (int o = 4; o > 0; o >>= 1) {
            a += __shfl_xor_sync(0xffffffffu, a, o);
            b += __shfl_xor_sync(0xffffffffu, b, o);
        }
        if (l == 0) { red[32] = a; red[33] = b; }
    }
    __syncthreads();
    float mu = red[32] * (1.0f / DIM);
    float var = red[33] * (1.0f / DIM) - mu * mu;
    float inv = rsqrtf(var + LN_EPS);
    row[tid]       = (v0 - mu) * inv * gamma[tid]       + beta[tid];
    row[tid + 256] = (v1 - mu) * inv * gamma[tid + 256] + beta[tid + 256];
    row[tid + 512] = (v2 - mu) * inv * gamma[tid + 512] + beta[tid + 512];
}

// ---------------------------------------------------------------------------
// kernel_launch
// ---------------------------------------------------------------------------
extern "C" void kernel_launch(void* const* d_in, const int* in_sizes, int n_in,
                              void* d_out, int out_size) {
    const float* X   = (const float*)d_in[0];
    const float* Wm  = (const float*)d_in[1];
    const float* bm  = (const float*)d_in[2];
    const float* Wu  = (const float*)d_in[3];
    const float* bu  = (const float*)d_in[4];
    const float* gam = (const float*)d_in[5];
    const float* bet = (const float*)d_in[6];
    const int*   eidx= (const int*)d_in[7];
    const int*   etyp= (const int*)d_in[8];
    float* out = (float*)d_out;

    (void)in_sizes; (void)n_in; (void)out_size;

    cudaFuncSetAttribute(k_msg, cudaFuncAttributeMaxDynamicSharedMemorySize, SMEM_SZ);
    cudaFuncSetAttribute(k_upd, cudaFuncAttributeMaxDynamicSharedMemorySize, SMEM_SZ);

    void* xtf;  cudaGetSymbolAddress(&xtf,  g_xtf_v);
    void* wmtf; cudaGetSymbolAddress(&wmtf, g_wmtf_v);
    void* wutf; cudaGetSymbolAddress(&wutf, g_wutf_v);

    k_init<<<4096, 256>>>();
    k_bucket<<<(NE + 255) / 256, 256>>>(etyp);

    // f32 -> fp16(rn) + K-permute all inputs in one launch
    k_cvtp3<<<4096, 256>>>(X,  (__half*)xtf,  (size_t)NN * DIM / 32,
                           Wm, (__half*)wmtf, (size_t)NT * DIM * DIM / 32,
                           Wu, (__half*)wutf, (size_t)DIM * DIM2 / 32);

    dim3 gm(DIM / BN, (NE + BM - 1) / BM, NT);
    k_msg<<<gm, THREADS, SMEM_SZ>>>(bm, eidx);

    dim3 gu(DIM / BN, (NN + BM - 1) / BM);
    k_upd<<<gu, THREADS, SMEM_SZ>>>(bu, out);

    k_ln<<<NN, 256>>>(out, X, gam, bet);
}

// round 16
// speedup vs baseline: 1.1581x; 1.1581x over previous
#include <cuda_runtime.h>
#include <cuda_fp16.h>
#include <cstdint>
#include <cstddef>

// ---------------------------------------------------------------------------
// Problem constants
// ---------------------------------------------------------------------------
#define NN   100000
#define NE   100000
#define DIM  768
#define DIM2 1536
#define NT   5
#define LN_EPS 1e-5f

// Shared GEMM geometry: CTA 128x128, BK=64 halves, 3 stages x 32KB,
// XOR-swizzled 16B chunks, 1 barrier/slice, 2 CTA/SM.
// k_msg: 256 threads, 8 warps 2x4, warp tile 64x32  (best measured for msg)
// k_upd: 128 threads, 4 warps 2x2, warp tile 64x64  (best measured for upd)
#define BM 128
#define BN 128
#define BK 64
#define ROWU 32                 // unsigned per smem row (128 B)
#define A_STG_BYTES (BM * 128)  // 16384
#define B_STG_BYTES (BN * 128)  // 16384
#define STG_BYTES   (A_STG_BYTES + B_STG_BYTES)  // 32768
#define SM_IDX   0
#define SM_TILES 1024
#define SMEM_SZ  (SM_TILES + 3 * STG_BYTES)      // 99328

// ---------------------------------------------------------------------------
// Device scratch (uint4 arrays for 16B alignment; viewed as __half).
// fp16 data K-PERMUTED within each 32-half group:
//   phys(l) = 8*((l>>1)&3) + 2*((l>>3)&3) + (l&1)
// ---------------------------------------------------------------------------
__device__ uint4 g_agg_v [(size_t)NN * DIM / 8];
__device__ uint4 g_xtf_v [(size_t)NN * DIM / 8];
__device__ uint4 g_wmtf_v[(size_t)NT * DIM * DIM / 8];
__device__ uint4 g_wutf_v[(size_t)DIM * DIM2 / 8];
__device__ int   g_bucket[NT][NE];
__device__ int   g_count[NT];

// ---------------------------------------------------------------------------
// Helpers
// ---------------------------------------------------------------------------
__device__ __forceinline__ uint32_t smem_u32(const void* p) {
    uint32_t a;
    asm("{ .reg .u64 t; cvta.to.shared.u64 t, %1; cvt.u32.u64 %0, t; }"
        : "=r"(a) : "l"(p));
    return a;
}

__device__ __forceinline__ void cpa16(uint32_t s, const void* g) {
    asm volatile("cp.async.cg.shared.global [%0], [%1], 16;"
                 :: "r"(s), "l"(g) : "memory");
}
__device__ __forceinline__ void cpa_commit() {
    asm volatile("cp.async.commit_group;" ::: "memory");
}
__device__ __forceinline__ void cpa_wait1() {
    asm volatile("cp.async.wait_group 1;" ::: "memory");
}
__device__ __forceinline__ void cpa_wait0() {
    asm volatile("cp.async.wait_group 0;" ::: "memory");
}

__device__ __forceinline__ void mma16(float& c0, float& c1, float& c2, float& c3,
                                      unsigned a0, unsigned a1, unsigned a2, unsigned a3,
                                      unsigned b0, unsigned b1) {
    asm volatile(
        "mma.sync.aligned.m16n8k16.row.col.f32.f16.f16.f32 "
        "{%0,%1,%2,%3}, {%4,%5,%6,%7}, {%8,%9}, {%0,%1,%2,%3};\n"
        : "+f"(c0), "+f"(c1), "+f"(c2), "+f"(c3)
        : "r"(a0), "r"(a1), "r"(a2), "r"(a3), "r"(b0), "r"(b1));
}

// BK=64 slice, 64x32 warp tile (k_msg)
__device__ __forceinline__ void stage_m(const unsigned* __restrict__ As,
                                        const unsigned* __restrict__ Bs,
                                        float c[4][4][4],
                                        int wm, int wn, int g, int tg) {
    int xorv = (g & 1) << 2;
#pragma unroll
    for (int kp = 0; kp < 2; ++kp) {
        int cu = ((4 * kp + tg) ^ xorv) * 4;
        uint4 a[4][2], b[4];
#pragma unroll
        for (int im = 0; im < 4; ++im) {
            int mb = wm * 64 + im * 16;
            a[im][0] = *reinterpret_cast<const uint4*>(&As[(mb + g) * ROWU + cu]);
            a[im][1] = *reinterpret_cast<const uint4*>(&As[(mb + g + 8) * ROWU + cu]);
        }
#pragma unroll
        for (int in_ = 0; in_ < 4; ++in_) {
            int nb = wn * 32 + in_ * 8 + g;
            b[in_] = *reinterpret_cast<const uint4*>(&Bs[nb * ROWU + cu]);
        }
#pragma unroll
        for (int im = 0; im < 4; ++im)
#pragma unroll
            for (int in_ = 0; in_ < 4; ++in_) {
                mma16(c[im][in_][0], c[im][in_][1], c[im][in_][2], c[im][in_][3],
                      a[im][0].x, a[im][1].x, a[im][0].y, a[im][1].y,
                      b[in_].x, b[in_].y);
                mma16(c[im][in_][0], c[im][in_][1], c[im][in_][2], c[im][in_][3],
                      a[im][0].z, a[im][1].z, a[im][0].w, a[im][1].w,
                      b[in_].z, b[in_].w);
            }
    }
}

// BK=64 slice, 64x64 warp tile (k_upd)
__device__ __forceinline__ void stage_u(const unsigned* __restrict__ As,
                                        const unsigned* __restrict__ Bs,
                                        float c[4][8][4],
                                        int wm, int wn, int g, int tg) {
    int xorv = (g & 1) << 2;
#pragma unroll
    for (int kp = 0; kp < 2; ++kp) {
        int cu = ((4 * kp + tg) ^ xorv) * 4;
        uint4 a[4][2], b[8];
#pragma unroll
        for (int im = 0; im < 4; ++im) {
            int mb = wm * 64 + im * 16;
            a[im][0] = *reinterpret_cast<const uint4*>(&As[(mb + g) * ROWU + cu]);
            a[im][1] = *reinterpret_cast<const uint4*>(&As[(mb + g + 8) * ROWU + cu]);
        }
#pragma unroll
        for (int in_ = 0; in_ < 8; ++in_) {
            int nb = wn * 64 + in_ * 8 + g;
            b[in_] = *reinterpret_cast<const uint4*>(&Bs[nb * ROWU + cu]);
        }
#pragma unroll
        for (int im = 0; im < 4; ++im)
#pragma unroll
            for (int in_ = 0; in_ < 8; ++in_) {
                mma16(c[im][in_][0], c[im][in_][1], c[im][in_][2], c[im][in_][3],
                      a[im][0].x, a[im][1].x, a[im][0].y, a[im][1].y,
                      b[in_].x, b[in_].y);
                mma16(c[im][in_][0], c[im][in_][1], c[im][in_][2], c[im][in_][3],
                      a[im][0].z, a[im][1].z, a[im][0].w, a[im][1].w,
                      b[in_].z, b[in_].w);
            }
    }
}

// ---------------------------------------------------------------------------
// K0 / K1: init + bucket
// ---------------------------------------------------------------------------
__global__ void k_init() {
    size_t idx = (size_t)blockIdx.x * blockDim.x + threadIdx.x;
    if (idx < NT) g_count[idx] = 0;
    size_t n = (size_t)NN * DIM / 8;
    size_t stride = (size_t)gridDim.x * blockDim.x;
    uint4 z = make_uint4(0, 0, 0, 0);
    for (size_t i = idx; i < n; i += stride) g_agg_v[i] = z;
}

__global__ void k_bucket(const int* __restrict__ etype) {
    int e = blockIdx.x * blockDim.x + threadIdx.x;
    if (e < NE) {
        int t = etype[e];
        int pos = atomicAdd(&g_count[t], 1);
        g_bucket[t][pos] = e;
    }
}

// f32 -> fp16(rn) + K-permute one 32-float group
__device__ __forceinline__ void cvtph_group(const float* src, __half* dst, size_t i) {
    const float4* s = reinterpret_cast<const float4*>(src) + i * 8;
    float in[32];
#pragma unroll
    for (int j = 0; j < 8; ++j) {
        float4 v = s[j];
        in[j * 4] = v.x; in[j * 4 + 1] = v.y; in[j * 4 + 2] = v.z; in[j * 4 + 3] = v.w;
    }
    __half2 out[16];
#pragma unroll
    for (int ph = 0; ph < 16; ++ph) {
        int p = ph * 2;
        int l = ((p >> 3) << 1) + (((p >> 1) & 3) << 3);
        out[ph] = __floats2half2_rn(in[l], in[l + 1]);
    }
    uint4* d = reinterpret_cast<uint4*>(dst + i * 32);
    const uint4* o = reinterpret_cast<const uint4*>(out);
    d[0] = o[0]; d[1] = o[1]; d[2] = o[2]; d[3] = o[3];
}

__global__ void k_cvtp3(const float* s0, __half* d0, size_t n0,
                        const float* s1, __half* d1, size_t n1,
                        const float* s2, __half* d2, size_t n2) {
    size_t idx = (size_t)blockIdx.x * blockDim.x + threadIdx.x;
    size_t stride = (size_t)gridDim.x * blockDim.x;
    size_t total = n0 + n1 + n2;
    for (size_t i = idx; i < total; i += stride) {
        if (i < n0) cvtph_group(s0, d0, i);
        else if (i < n0 + n1) cvtph_group(s1, d1, i - n0);
        else cvtph_group(s2, d2, i - n0 - n1);
    }
}

// ---------------------------------------------------------------------------
// K2: per-type gather-GEMM (fp16); epilogue rounds to fp16 and half2-atomic
//     scatter-adds into PERMUTED g_agg. grid (6, 782, 5), 256 thr, 2 CTA/SM
// ---------------------------------------------------------------------------
__global__ __launch_bounds__(256, 2) void k_msg(const float* __restrict__ bm,
                                                const int*   __restrict__ eidx) {
    int t = blockIdx.z;
    int cnt = g_count[t];
    int m0 = blockIdx.y * BM;
    if (m0 >= cnt) return;
    int n0 = blockIdx.x * BN;

    extern __shared__ char smem[];
    uint32_t sb = smem_u32(smem);
    int* s_src = (int*)(smem + SM_IDX);
    int* s_tgt = (int*)(smem + SM_IDX + 512);

    int tid = threadIdx.x, lane = tid & 31, w = tid >> 5;
    int wm = w >> 2, wn = w & 3;
    int g = lane >> 2, tg = lane & 3;

    if (tid < BM) {
        int slot = m0 + tid;
        if (slot < cnt) {
            int e = g_bucket[t][slot];
            s_src[tid] = eidx[e];
            s_tgt[tid] = eidx[NE + e];
        } else {
            s_src[tid] = 0;
            s_tgt[tid] = -1;
        }
    }
    __syncthreads();

    const __half* Xh = (const __half*)g_xtf_v;
    const __half* Wt = (const __half*)g_wmtf_v + (size_t)t * DIM * DIM;

    // fill: 128 rows x 8 chunks = 1024 chunks each; 256 threads x p<4
    auto fill = [&](int stg, int kk) {
        uint32_t ab = sb + SM_TILES + stg * STG_BYTES;
        uint32_t bbs = ab + A_STG_BYTES;
#pragma unroll
        for (int p = 0; p < 4; ++p) {
            int f = p * 256 + tid;
            int row = f >> 3, q = f & 7;
            int qs = q ^ ((row & 1) << 2);
            cpa16(ab + row * 128 + qs * 16,
                  Xh + (size_t)s_src[row] * DIM + kk + q * 8);
        }
#pragma unroll
        for (int p = 0; p < 4; ++p) {
            int f = p * 256 + tid;
            int row = f >> 3, q = f & 7;
            int qs = q ^ ((row & 1) << 2);
            cpa16(bbs + row * 128 + qs * 16,
                  Wt + (size_t)(n0 + row) * DIM + kk + q * 8);
        }
    };

    float c[4][4][4];
#pragma unroll
    for (int i = 0; i < 4; i++)
#pragma unroll
        for (int j = 0; j < 4; j++)
#pragma unroll
            for (int r = 0; r < 4; r++) c[i][j][r] = 0.f;

    const int KT = DIM / BK;   // 12
    fill(0, 0); cpa_commit();
    fill(1, BK); cpa_commit();

    for (int kt = 0; kt < KT; ++kt) {
        if (kt == KT - 1) cpa_wait0(); else cpa_wait1();
        __syncthreads();
        const unsigned* As = (const unsigned*)(smem + SM_TILES + (kt % 3) * STG_BYTES);
        const unsigned* Bs = As + BM * ROWU;
        stage_m(As, Bs, c, wm, wn, g, tg);
        if (kt + 2 < KT) fill((kt + 2) % 3, (kt + 2) * BK);
        cpa_commit();
    }

    // epilogue: + bias, fp16-round, half2 atomic into PERMUTED g_agg.
    __half* aggh = (__half*)g_agg_v;
#pragma unroll
    for (int im = 0; im < 4; ++im) {
#pragma unroll
        for (int r2 = 0; r2 < 2; ++r2) {
            int rloc = wm * 64 + im * 16 + g + r2 * 8;
            int tgt = s_tgt[rloc];
            if (tgt < 0) continue;
            __half* dst = aggh + (size_t)tgt * DIM;
#pragma unroll
            for (int in_ = 0; in_ < 4; ++in_) {
                int col = n0 + wn * 32 + in_ * 8 + tg * 2;
                int base = col & ~31;
                int l32 = col & 31;
                int p = (((l32 >> 1) & 3) << 3) + (((l32 >> 3) & 3) << 1);
                float v0 = c[im][in_][r2 * 2 + 0] + bm[t * DIM + col];
                float v1 = c[im][in_][r2 * 2 + 1] + bm[t * DIM + col + 1];
                atomicAdd(reinterpret_cast<__half2*>(dst + base + p),
                          __floats2half2_rn(v0, v1));
            }
        }
    }
}

// ---------------------------------------------------------------------------
// K3: update GEMM (fp16)  out = X + relu([X | agg] @ W_upd^T + b_upd)
//     (residual FUSED here). grid (6, 782), 128 threads, 2 CTA/SM
// ---------------------------------------------------------------------------
__global__ __launch_bounds__(128, 2) void k_upd(const float* __restrict__ X,
                                                const float* __restrict__ bu,
                                                float* __restrict__ out) {
    int m0 = blockIdx.y * BM;
    int n0 = blockIdx.x * BN;

    extern __shared__ char smem[];
    uint32_t sb = smem_u32(smem);

    int tid = threadIdx.x, lane = tid & 31, w = tid >> 5;
    int wm = w >> 1, wn = w & 1;
    int g = lane >> 2, tg = lane & 3;

    const __half* Xh = (const __half*)g_xtf_v;
    const __half* Ah = (const __half*)g_agg_v;
    const __half* Wu = (const __half*)g_wutf_v;

    // fill: 128 rows x 8 chunks = 1024 chunks each; 128 threads x p<8
    auto fill = [&](int stg, int kk) {
        uint32_t ab = sb + SM_TILES + stg * STG_BYTES;
        uint32_t bbs = ab + A_STG_BYTES;
        const __half* abase = (kk < DIM) ? Xh + kk : Ah + (kk - DIM);
#pragma unroll
        for (int p = 0; p < 8; ++p) {
            int f = p * 128 + tid;
            int row = f >> 3, q = f & 7;
            int qs = q ^ ((row & 1) << 2);
            int node = m0 + row; if (node >= NN) node = NN - 1;
            cpa16(ab + row * 128 + qs * 16, abase + (size_t)node * DIM + q * 8);
        }
#pragma unroll
        for (int p = 0; p < 8; ++p) {
            int f = p * 128 + tid;
            int row = f >> 3, q = f & 7;
            int qs = q ^ ((row & 1) << 2);
            cpa16(bbs + row * 128 + qs * 16,
                  Wu + (size_t)(n0 + row) * DIM2 + kk + q * 8);
        }
    };

    float c[4][8][4];
#pragma unroll
    for (int i = 0; i < 4; i++)
#pragma unroll
        for (int j = 0; j < 8; j++)
#pragma unroll
            for (int r = 0; r < 4; r++) c[i][j][r] = 0.f;

    const int KT = DIM2 / BK;  // 24
    fill(0, 0); cpa_commit();
    fill(1, BK); cpa_commit();

    for (int kt = 0; kt < KT; ++kt) {
        if (kt == KT - 1) cpa_wait0(); else cpa_wait1();
        __syncthreads();
        const unsigned* As = (const unsigned*)(smem + SM_TILES + (kt % 3) * STG_BYTES);
        const unsigned* Bs = As + BM * ROWU;
        stage_u(As, Bs, c, wm, wn, g, tg);
        if (kt + 2 < KT) fill((kt + 2) % 3, (kt + 2) * BK);
        cpa_commit();
    }

    // epilogue: bias + relu + residual (f32 X), float2 stores
#pragma unroll
    for (int im = 0; im < 4; ++im) {
#pragma unroll
        for (int r2 = 0; r2 < 2; ++r2) {
            int rloc = wm * 64 + im * 16 + g + r2 * 8;
            int node = m0 + rloc;
            if (node >= NN) continue;
#pragma unroll
            for (int in_ = 0; in_ < 8; ++in_) {
                int col = n0 + wn * 64 + in_ * 8 + tg * 2;
                float2 xres = *reinterpret_cast<const float2*>(
                    X + (size_t)node * DIM + col);
                float2 o;
                o.x = fmaxf(c[im][in_][r2 * 2 + 0] + bu[col],     0.f) + xres.x;
                o.y = fmaxf(c[im][in_][r2 * 2 + 1] + bu[col + 1], 0.f) + xres.y;
                *reinterpret_cast<float2*>(out + (size_t)node * DIM + col) = o;
            }
        }
    }
}

// ---------------------------------------------------------------------------
// K4: out = LayerNorm(out)  (residual already folded by k_upd)
//     192 threads x float4 = 768 elements
// ---------------------------------------------------------------------------
__global__ __launch_bounds__(192) void k_ln(float* __restrict__ out,
                                            const float* __restrict__ gamma,
                                            const float* __restrict__ beta) {
    __shared__ float red[16];
    int n = blockIdx.x;
    int tid = threadIdx.x;
    float* row = out + (size_t)n * DIM;

    float4 v = *reinterpret_cast<const float4*>(row + tid * 4);
    float s = v.x + v.y + v.z + v.w;
    float s2 = v.x * v.x + v.y * v.y + v.z * v.z + v.w * v.w;
#pragma unroll
    for (int o = 16; o > 0; o >>= 1) {
        s  += __shfl_xor_sync(0xffffffffu, s, o);
        s2 += __shfl_xor_sync(0xffffffffu, s2, o);
    }
    int w = tid >> 5, l = tid & 31;
    if (l == 0) { red[w] = s; red[8 + w] = s2; }
    __syncthreads();
    if (w == 0) {
        float a = (l < 6) ? red[l] : 0.f;
        float b = (l < 6) ? red[8 + l] : 0.f;
#pragma unroll
        for (int o = 4; o > 0; o >>= 1) {
            a += __shfl_xor_sync(0xffffffffu, a, o);
            b += __shfl_xor_sync(0xffffffffu, b, o);
        }
        if (l == 0) { red[14] = a; red[15] = b; }
    }
    __syncthreads();
    float mu = red[14] * (1.0f / DIM);
    float var = red[15] * (1.0f / DIM) - mu * mu;
    float inv = rsqrtf(var + LN_EPS);
    float4 gm = *reinterpret_cast<const float4*>(gamma + tid * 4);
    float4 bt = *reinterpret_cast<const float4*>(beta + tid * 4);
    float4 o;
    o.x = (v.x - mu) * inv * gm.x + bt.x;
    o.y = (v.y - mu) * inv * gm.y + bt.y;
    o.z = (v.z - mu) * inv * gm.z + bt.z;
    o.w = (v.w - mu) * inv * gm.w + bt.w;
    *reinterpret_cast<float4*>(row + tid * 4) = o;
}

// ---------------------------------------------------------------------------
// kernel_launch
// ---------------------------------------------------------------------------
extern "C" void kernel_launch(void* const* d_in, const int* in_sizes, int n_in,
                              void* d_out, int out_size) {
    const float* X   = (const float*)d_in[0];
    const float* Wm  = (const float*)d_in[1];
    const float* bm  = (const float*)d_in[2];
    const float* Wu  = (const float*)d_in[3];
    const float* bu  = (const float*)d_in[4];
    const float* gam = (const float*)d_in[5];
    const float* bet = (const float*)d_in[6];
    const int*   eidx= (const int*)d_in[7];
    const int*   etyp= (const int*)d_in[8];
    float* out = (float*)d_out;

    (void)in_sizes; (void)n_in; (void)out_size;

    cudaFuncSetAttribute(k_msg, cudaFuncAttributeMaxDynamicSharedMemorySize, SMEM_SZ);
    cudaFuncSetAttribute(k_upd, cudaFuncAttributeMaxDynamicSharedMemorySize, SMEM_SZ);

    void* xtf;  cudaGetSymbolAddress(&xtf,  g_xtf_v);
    void* wmtf; cudaGetSymbolAddress(&wmtf, g_wmtf_v);
    void* wutf; cudaGetSymbolAddress(&wutf, g_wutf_v);

    k_init<<<4096, 256>>>();
    k_bucket<<<(NE + 255) / 256, 256>>>(etyp);

    // f32 -> fp16(rn) + K-permute all inputs in one launch
    k_cvtp3<<<4096, 256>>>(X,  (__half*)xtf,  (size_t)NN * DIM / 32,
                           Wm, (__half*)wmtf, (size_t)NT * DIM * DIM / 32,
                           Wu, (__half*)wutf, (size_t)DIM * DIM2 / 32);

    dim3 gm(DIM / BN, (NE + BM - 1) / BM, NT);
    k_msg<<<gm, 256, SMEM_SZ>>>(bm, eidx);

    dim3 gu(DIM / BN, (NN + BM - 1) / BM);
    k_upd<<<gu, 128, SMEM_SZ>>>(X, bu, out);

    k_ln<<<NN, 192>>>(out, gam, bet);
}

// round 17
// speedup vs baseline: 1.2374x; 1.0685x over previous
#include <cuda_runtime.h>
#include <cuda_fp16.h>
#include <cstdint>
#include <cstddef>

// ---------------------------------------------------------------------------
// Problem constants
// ---------------------------------------------------------------------------
#define NN   100000
#define NE   100000
#define DIM  768
#define DIM2 1536
#define NT   5
#define LN_EPS 1e-5f

// Shared GEMM geometry: CTA 128x128, BK=64 halves, 3 stages x 32KB,
// XOR-swizzled 16B chunks, 1 barrier/slice, 2 CTA/SM.
// k_msg: 256 threads, 8 warps 2x4, warp tile 64x32
// k_upd: 128 threads, 4 warps 2x2, warp tile 64x64
#define BM 128
#define BN 128
#define BK 64
#define ROWU 32                 // unsigned per smem row (128 B)
#define A_STG_BYTES (BM * 128)  // 16384
#define B_STG_BYTES (BN * 128)  // 16384
#define STG_BYTES   (A_STG_BYTES + B_STG_BYTES)  // 32768
#define SM_IDX   0
#define SM_TILES 1024
#define SMEM_SZ  (SM_TILES + 3 * STG_BYTES)      // 99328

// ---------------------------------------------------------------------------
// Device scratch (uint4 arrays for 16B alignment; viewed as __half).
// fp16 data K-PERMUTED within each 32-half group:
//   phys(l) = 8*((l>>1)&3) + 2*((l>>3)&3) + (l&1)
// Inverse property used in k_msg epilogue: for l = in_*8 + tg*2 (+bit),
//   phys = 8*tg + 2*in_ + bit  -> a thread's 4 half2 (in_=0..3) are one
//   contiguous 16B-aligned chunk at half-offset 8*tg.
// ---------------------------------------------------------------------------
__device__ uint4 g_agg_v [(size_t)NN * DIM / 8];
__device__ uint4 g_xtf_v [(size_t)NN * DIM / 8];
__device__ uint4 g_wmtf_v[(size_t)NT * DIM * DIM / 8];
__device__ uint4 g_wutf_v[(size_t)DIM * DIM2 / 8];
__device__ int   g_bucket[NT][NE];
__device__ int   g_count[NT];

// ---------------------------------------------------------------------------
// Helpers
// ---------------------------------------------------------------------------
__device__ __forceinline__ uint32_t smem_u32(const void* p) {
    uint32_t a;
    asm("{ .reg .u64 t; cvta.to.shared.u64 t, %1; cvt.u32.u64 %0, t; }"
        : "=r"(a) : "l"(p));
    return a;
}

__device__ __forceinline__ void cpa16(uint32_t s, const void* g) {
    asm volatile("cp.async.cg.shared.global [%0], [%1], 16;"
                 :: "r"(s), "l"(g) : "memory");
}
__device__ __forceinline__ void cpa_commit() {
    asm volatile("cp.async.commit_group;" ::: "memory");
}
__device__ __forceinline__ void cpa_wait1() {
    asm volatile("cp.async.wait_group 1;" ::: "memory");
}
__device__ __forceinline__ void cpa_wait0() {
    asm volatile("cp.async.wait_group 0;" ::: "memory");
}

__device__ __forceinline__ void mma16(float& c0, float& c1, float& c2, float& c3,
                                      unsigned a0, unsigned a1, unsigned a2, unsigned a3,
                                      unsigned b0, unsigned b1) {
    asm volatile(
        "mma.sync.aligned.m16n8k16.row.col.f32.f16.f16.f32 "
        "{%0,%1,%2,%3}, {%4,%5,%6,%7}, {%8,%9}, {%0,%1,%2,%3};\n"
        : "+f"(c0), "+f"(c1), "+f"(c2), "+f"(c3)
        : "r"(a0), "r"(a1), "r"(a2), "r"(a3), "r"(b0), "r"(b1));
}

// one 16B vector fp16 reduction: 8 halves in one atomic op (sm_90+)
__device__ __forceinline__ void red_v4h2(__half* addr, unsigned h0, unsigned h1,
                                         unsigned h2, unsigned h3) {
    asm volatile("red.global.add.noftz.v4.f16x2 [%0], {%1, %2, %3, %4};"
                 :: "l"(addr), "r"(h0), "r"(h1), "r"(h2), "r"(h3) : "memory");
}

// BK=64 slice, 64x32 warp tile (k_msg)
__device__ __forceinline__ void stage_m(const unsigned* __restrict__ As,
                                        const unsigned* __restrict__ Bs,
                                        float c[4][4][4],
                                        int wm, int wn, int g, int tg) {
    int xorv = (g & 1) << 2;
#pragma unroll
    for (int kp = 0; kp < 2; ++kp) {
        int cu = ((4 * kp + tg) ^ xorv) * 4;
        uint4 a[4][2], b[4];
#pragma unroll
        for (int im = 0; im < 4; ++im) {
            int mb = wm * 64 + im * 16;
            a[im][0] = *reinterpret_cast<const uint4*>(&As[(mb + g) * ROWU + cu]);
            a[im][1] = *reinterpret_cast<const uint4*>(&As[(mb + g + 8) * ROWU + cu]);
        }
#pragma unroll
        for (int in_ = 0; in_ < 4; ++in_) {
            int nb = wn * 32 + in_ * 8 + g;
            b[in_] = *reinterpret_cast<const uint4*>(&Bs[nb * ROWU + cu]);
        }
#pragma unroll
        for (int im = 0; im < 4; ++im)
#pragma unroll
            for (int in_ = 0; in_ < 4; ++in_) {
                mma16(c[im][in_][0], c[im][in_][1], c[im][in_][2], c[im][in_][3],
                      a[im][0].x, a[im][1].x, a[im][0].y, a[im][1].y,
                      b[in_].x, b[in_].y);
                mma16(c[im][in_][0], c[im][in_][1], c[im][in_][2], c[im][in_][3],
                      a[im][0].z, a[im][1].z, a[im][0].w, a[im][1].w,
                      b[in_].z, b[in_].w);
            }
    }
}

// BK=64 slice, 64x64 warp tile (k_upd)
__device__ __forceinline__ void stage_u(const unsigned* __restrict__ As,
                                        const unsigned* __restrict__ Bs,
                                        float c[4][8][4],
                                        int wm, int wn, int g, int tg) {
    int xorv = (g & 1) << 2;
#pragma unroll
    for (int kp = 0; kp < 2; ++kp) {
        int cu = ((4 * kp + tg) ^ xorv) * 4;
        uint4 a[4][2], b[8];
#pragma unroll
        for (int im = 0; im < 4; ++im) {
            int mb = wm * 64 + im * 16;
            a[im][0] = *reinterpret_cast<const uint4*>(&As[(mb + g) * ROWU + cu]);
            a[im][1] = *reinterpret_cast<const uint4*>(&As[(mb + g + 8) * ROWU + cu]);
        }
#pragma unroll
        for (int in_ = 0; in_ < 8; ++in_) {
            int nb = wn * 64 + in_ * 8 + g;
            b[in_] = *reinterpret_cast<const uint4*>(&Bs[nb * ROWU + cu]);
        }
#pragma unroll
        for (int im = 0; im < 4; ++im)
#pragma unroll
            for (int in_ = 0; in_ < 8; ++in_) {
                mma16(c[im][in_][0], c[im][in_][1], c[im][in_][2], c[im][in_][3],
                      a[im][0].x, a[im][1].x, a[im][0].y, a[im][1].y,
                      b[in_].x, b[in_].y);
                mma16(c[im][in_][0], c[im][in_][1], c[im][in_][2], c[im][in_][3],
                      a[im][0].z, a[im][1].z, a[im][0].w, a[im][1].w,
                      b[in_].z, b[in_].w);
            }
    }
}

// ---------------------------------------------------------------------------
// K0 / K1: init + bucket
// ---------------------------------------------------------------------------
__global__ void k_init() {
    size_t idx = (size_t)blockIdx.x * blockDim.x + threadIdx.x;
    if (idx < NT) g_count[idx] = 0;
    size_t n = (size_t)NN * DIM / 8;
    size_t stride = (size_t)gridDim.x * blockDim.x;
    uint4 z = make_uint4(0, 0, 0, 0);
    for (size_t i = idx; i < n; i += stride) g_agg_v[i] = z;
}

__global__ void k_bucket(const int* __restrict__ etype) {
    int e = blockIdx.x * blockDim.x + threadIdx.x;
    if (e < NE) {
        int t = etype[e];
        int pos = atomicAdd(&g_count[t], 1);
        g_bucket[t][pos] = e;
    }
}

// f32 -> fp16(rn) + K-permute one 32-float group
__device__ __forceinline__ void cvtph_group(const float* src, __half* dst, size_t i) {
    const float4* s = reinterpret_cast<const float4*>(src) + i * 8;
    float in[32];
#pragma unroll
    for (int j = 0; j < 8; ++j) {
        float4 v = s[j];
        in[j * 4] = v.x; in[j * 4 + 1] = v.y; in[j * 4 + 2] = v.z; in[j * 4 + 3] = v.w;
    }
    __half2 out[16];
#pragma unroll
    for (int ph = 0; ph < 16; ++ph) {
        int p = ph * 2;
        int l = ((p >> 3) << 1) + (((p >> 1) & 3) << 3);
        out[ph] = __floats2half2_rn(in[l], in[l + 1]);
    }
    uint4* d = reinterpret_cast<uint4*>(dst + i * 32);
    const uint4* o = reinterpret_cast<const uint4*>(out);
    d[0] = o[0]; d[1] = o[1]; d[2] = o[2]; d[3] = o[3];
}

__global__ void k_cvtp3(const float* s0, __half* d0, size_t n0,
                        const float* s1, __half* d1, size_t n1,
                        const float* s2, __half* d2, size_t n2) {
    size_t idx = (size_t)blockIdx.x * blockDim.x + threadIdx.x;
    size_t stride = (size_t)gridDim.x * blockDim.x;
    size_t total = n0 + n1 + n2;
    for (size_t i = idx; i < total; i += stride) {
        if (i < n0) cvtph_group(s0, d0, i);
        else if (i < n0 + n1) cvtph_group(s1, d1, i - n0);
        else cvtph_group(s2, d2, i - n0 - n1);
    }
}

// ---------------------------------------------------------------------------
// K2: per-type gather-GEMM (fp16); epilogue rounds to fp16 and issues ONE
//     16B red.global.add.v4.f16x2 per (im,r2) into PERMUTED g_agg.
//     grid (6, 782, 5), 256 thr, 2 CTA/SM
// ---------------------------------------------------------------------------
__global__ __launch_bounds__(256, 2) void k_msg(const float* __restrict__ bm,
                                                const int*   __restrict__ eidx) {
    int t = blockIdx.z;
    int cnt = g_count[t];
    int m0 = blockIdx.y * BM;
    if (m0 >= cnt) return;
    int n0 = blockIdx.x * BN;

    extern __shared__ char smem[];
    uint32_t sb = smem_u32(smem);
    int* s_src = (int*)(smem + SM_IDX);
    int* s_tgt = (int*)(smem + SM_IDX + 512);

    int tid = threadIdx.x, lane = tid & 31, w = tid >> 5;
    int wm = w >> 2, wn = w & 3;
    int g = lane >> 2, tg = lane & 3;

    if (tid < BM) {
        int slot = m0 + tid;
        if (slot < cnt) {
            int e = g_bucket[t][slot];
            s_src[tid] = eidx[e];
            s_tgt[tid] = eidx[NE + e];
        } else {
            s_src[tid] = 0;
            s_tgt[tid] = -1;
        }
    }
    __syncthreads();

    const __half* Xh = (const __half*)g_xtf_v;
    const __half* Wt = (const __half*)g_wmtf_v + (size_t)t * DIM * DIM;

    auto fill = [&](int stg, int kk) {
        uint32_t ab = sb + SM_TILES + stg * STG_BYTES;
        uint32_t bbs = ab + A_STG_BYTES;
#pragma unroll
        for (int p = 0; p < 4; ++p) {
            int f = p * 256 + tid;
            int row = f >> 3, q = f & 7;
            int qs = q ^ ((row & 1) << 2);
            cpa16(ab + row * 128 + qs * 16,
                  Xh + (size_t)s_src[row] * DIM + kk + q * 8);
        }
#pragma unroll
        for (int p = 0; p < 4; ++p) {
            int f = p * 256 + tid;
            int row = f >> 3, q = f & 7;
            int qs = q ^ ((row & 1) << 2);
            cpa16(bbs + row * 128 + qs * 16,
                  Wt + (size_t)(n0 + row) * DIM + kk + q * 8);
        }
    };

    float c[4][4][4];
#pragma unroll
    for (int i = 0; i < 4; i++)
#pragma unroll
        for (int j = 0; j < 4; j++)
#pragma unroll
            for (int r = 0; r < 4; r++) c[i][j][r] = 0.f;

    const int KT = DIM / BK;   // 12
    fill(0, 0); cpa_commit();
    fill(1, BK); cpa_commit();

    for (int kt = 0; kt < KT; ++kt) {
        if (kt == KT - 1) cpa_wait0(); else cpa_wait1();
        __syncthreads();
        const unsigned* As = (const unsigned*)(smem + SM_TILES + (kt % 3) * STG_BYTES);
        const unsigned* Bs = As + BM * ROWU;
        stage_m(As, Bs, c, wm, wn, g, tg);
        if (kt + 2 < KT) fill((kt + 2) % 3, (kt + 2) * BK);
        cpa_commit();
    }

    // epilogue: + bias, fp16-round, ONE v4.f16x2 reduction per (im, r2).
    // This thread's columns all lie in the 32-group starting at n0+wn*32;
    // permuted offsets are 8*tg + 2*in_ + bit -> contiguous 8 halves.
    __half* aggh = (__half*)g_agg_v;
    int gbase = n0 + wn * 32;          // 32-aligned group base (logical==phys base)
#pragma unroll
    for (int im = 0; im < 4; ++im) {
#pragma unroll
        for (int r2 = 0; r2 < 2; ++r2) {
            int rloc = wm * 64 + im * 16 + g + r2 * 8;
            int tgt = s_tgt[rloc];
            if (tgt < 0) continue;
            unsigned h[4];
#pragma unroll
            for (int in_ = 0; in_ < 4; ++in_) {
                int col = gbase + in_ * 8 + tg * 2;
                float v0 = c[im][in_][r2 * 2 + 0] + bm[t * DIM + col];
                float v1 = c[im][in_][r2 * 2 + 1] + bm[t * DIM + col + 1];
                __half2 p = __floats2half2_rn(v0, v1);
                h[in_] = *reinterpret_cast<unsigned*>(&p);
            }
            __half* addr = aggh + (size_t)tgt * DIM + gbase + 8 * tg;
            red_v4h2(addr, h[0], h[1], h[2], h[3]);
        }
    }
}

// ---------------------------------------------------------------------------
// K3: update GEMM (fp16)  out = X + relu([X | agg] @ W_upd^T + b_upd)
//     (residual fused). grid (6, 782), 128 threads, 2 CTA/SM
// ---------------------------------------------------------------------------
__global__ __launch_bounds__(128, 2) void k_upd(const float* __restrict__ X,
                                                const float* __restrict__ bu,
                                                float* __restrict__ out) {
    int m0 = blockIdx.y * BM;
    int n0 = blockIdx.x * BN;

    extern __shared__ char smem[];
    uint32_t sb = smem_u32(smem);

    int tid = threadIdx.x, lane = tid & 31, w = tid >> 5;
    int wm = w >> 1, wn = w & 1;
    int g = lane >> 2, tg = lane & 3;

    const __half* Xh = (const __half*)g_xtf_v;
    const __half* Ah = (const __half*)g_agg_v;
    const __half* Wu = (const __half*)g_wutf_v;

    auto fill = [&](int stg, int kk) {
        uint32_t ab = sb + SM_TILES + stg * STG_BYTES;
        uint32_t bbs = ab + A_STG_BYTES;
        const __half* abase = (kk < DIM) ? Xh + kk : Ah + (kk - DIM);
#pragma unroll
        for (int p = 0; p < 8; ++p) {
            int f = p * 128 + tid;
            int row = f >> 3, q = f & 7;
            int qs = q ^ ((row & 1) << 2);
            int node = m0 + row; if (node >= NN) node = NN - 1;
            cpa16(ab + row * 128 + qs * 16, abase + (size_t)node * DIM + q * 8);
        }
#pragma unroll
        for (int p = 0; p < 8; ++p) {
            int f = p * 128 + tid;
            int row = f >> 3, q = f & 7;
            int qs = q ^ ((row & 1) << 2);
            cpa16(bbs + row * 128 + qs * 16,
                  Wu + (size_t)(n0 + row) * DIM2 + kk + q * 8);
        }
    };

    float c[4][8][4];
#pragma unroll
    for (int i = 0; i < 4; i++)
#pragma unroll
        for (int j = 0; j < 8; j++)
#pragma unroll
            for (int r = 0; r < 4; r++) c[i][j][r] = 0.f;

    const int KT = DIM2 / BK;  // 24
    fill(0, 0); cpa_commit();
    fill(1, BK); cpa_commit();

    for (int kt = 0; kt < KT; ++kt) {
        if (kt == KT - 1) cpa_wait0(); else cpa_wait1();
        __syncthreads();
        const unsigned* As = (const unsigned*)(smem + SM_TILES + (kt % 3) * STG_BYTES);
        const unsigned* Bs = As + BM * ROWU;
        stage_u(As, Bs, c, wm, wn, g, tg);
        if (kt + 2 < KT) fill((kt + 2) % 3, (kt + 2) * BK);
        cpa_commit();
    }

    // epilogue: bias + relu + residual (f32 X), float2 stores
#pragma unroll
    for (int im = 0; im < 4; ++im) {
#pragma unroll
        for (int r2 = 0; r2 < 2; ++r2) {
            int rloc = wm * 64 + im * 16 + g + r2 * 8;
            int node = m0 + rloc;
            if (node >= NN) continue;
#pragma unroll
            for (int in_ = 0; in_ < 8; ++in_) {
                int col = n0 + wn * 64 + in_ * 8 + tg * 2;
                float2 xres = *reinterpret_cast<const float2*>(
                    X + (size_t)node * DIM + col);
                float2 o;
                o.x = fmaxf(c[im][in_][r2 * 2 + 0] + bu[col],     0.f) + xres.x;
                o.y = fmaxf(c[im][in_][r2 * 2 + 1] + bu[col + 1], 0.f) + xres.y;
                *reinterpret_cast<float2*>(out + (size_t)node * DIM + col) = o;
            }
        }
    }
}

// ---------------------------------------------------------------------------
// K4: out = LayerNorm(out)   192 threads x float4
// ---------------------------------------------------------------------------
__global__ __launch_bounds__(192) void k_ln(float* __restrict__ out,
                                            const float* __restrict__ gamma,
                                            const float* __restrict__ beta) {
    __shared__ float red[16];
    int n = blockIdx.x;
    int tid = threadIdx.x;
    float* row = out + (size_t)n * DIM;

    float4 v = *reinterpret_cast<const float4*>(row + tid * 4);
    float s = v.x + v.y + v.z + v.w;
    float s2 = v.x * v.x + v.y * v.y + v.z * v.z + v.w * v.w;
#pragma unroll
    for (int o = 16; o > 0; o >>= 1) {
        s  += __shfl_xor_sync(0xffffffffu, s, o);
        s2 += __shfl_xor_sync(0xffffffffu, s2, o);
    }
    int w = tid >> 5, l = tid & 31;
    if (l == 0) { red[w] = s; red[8 + w] = s2; }
    __syncthreads();
    if (w == 0) {
        float a = (l < 6) ? red[l] : 0.f;
        float b = (l < 6) ? red[8 + l] : 0.f;
#pragma unroll
        for (int o = 4; o > 0; o >>= 1) {
            a += __shfl_xor_sync(0xffffffffu, a, o);
            b += __shfl_xor_sync(0xffffffffu, b, o);
        }
        if (l == 0) { red[14] = a; red[15] = b; }
    }
    __syncthreads();
    float mu = red[14] * (1.0f / DIM);
    float var = red[15] * (1.0f / DIM) - mu * mu;
    float inv = rsqrtf(var + LN_EPS);
    float4 gm = *reinterpret_cast<const float4*>(gamma + tid * 4);
    float4 bt = *reinterpret_cast<const float4*>(beta + tid * 4);
    float4 o;
    o.x = (v.x - mu) * inv * gm.x + bt.x;
    o.y = (v.y - mu) * inv * gm.y + bt.y;
    o.z = (v.z - mu) * inv * gm.z + bt.z;
    o.w = (v.w - mu) * inv * gm.w + bt.w;
    *reinterpret_cast<float4*>(row + tid * 4) = o;
}

// ---------------------------------------------------------------------------
// kernel_launch
// ---------------------------------------------------------------------------
extern "C" void kernel_launch(void* const* d_in, const int* in_sizes, int n_in,
                              void* d_out, int out_size) {
    const float* X   = (const float*)d_in[0];
    const float* Wm  = (const float*)d_in[1];
    const float* bm  = (const float*)d_in[2];
    const float* Wu  = (const float*)d_in[3];
    const float* bu  = (const float*)d_in[4];
    const float* gam = (const float*)d_in[5];
    const float* bet = (const float*)d_in[6];
    const int*   eidx= (const int*)d_in[7];
    const int*   etyp= (const int*)d_in[8];
    float* out = (float*)d_out;

    (void)in_sizes; (void)n_in; (void)out_size;

    cudaFuncSetAttribute(k_msg, cudaFuncAttributeMaxDynamicSharedMemorySize, SMEM_SZ);
    cudaFuncSetAttribute(k_upd, cudaFuncAttributeMaxDynamicSharedMemorySize, SMEM_SZ);

    void* xtf;  cudaGetSymbolAddress(&xtf,  g_xtf_v);
    void* wmtf; cudaGetSymbolAddress(&wmtf, g_wmtf_v);
    void* wutf; cudaGetSymbolAddress(&wutf, g_wutf_v);

    k_init<<<4096, 256>>>();
    k_bucket<<<(NE + 255) / 256, 256>>>(etyp);

    // f32 -> fp16(rn) + K-permute all inputs in one launch
    k_cvtp3<<<4096, 256>>>(X,  (__half*)xtf,  (size_t)NN * DIM / 32,
                           Wm, (__half*)wmtf, (size_t)NT * DIM * DIM / 32,
                           Wu, (__half*)wutf, (size_t)DIM * DIM2 / 32);

    dim3 gm(DIM / BN, (NE + BM - 1) / BM, NT);
    k_msg<<<gm, 256, SMEM_SZ>>>(bm, eidx);

    dim3 gu(DIM / BN, (NN + BM - 1) / BM);
    k_upd<<<gu, 128, SMEM_SZ>>>(X, bu, out);

    k_ln<<<NN, 192>>>(out, gam, bet);
}